// round 4
// baseline (speedup 1.0000x reference)
#include <cuda_runtime.h>
#include <math.h>
#include <stdint.h>

#define B_  2
#define L_  2048
#define D_  1024
#define H_  16
#define DH_ 64
#define R_  (B_ * L_)          // 4096 rows total
#define D3_ (3 * D_)           // 3072

// ---------------- scratch (device globals; no allocation allowed) -----------
__device__ float g_h[(size_t)R_ * D_];        // 16 MB  : LN1 output
__device__ float g_qkv[(size_t)R_ * D3_];     // 48 MB  : qkv (q/k rewritten in place)
__device__ float g_ctx[(size_t)R_ * D_];      // 16 MB  : attention context
__device__ float g_cos[L_ * 32];
__device__ float g_sin[L_ * 32];

// ---------------- helpers ---------------------------------------------------
__device__ __forceinline__ float to_tf32(float x) {
    uint32_t u;
    asm("cvt.rna.tf32.f32 %0, %1;" : "=r"(u) : "f"(x));
    return __uint_as_float(u);
}

// m16n8k8 tf32 mma, fp32 accumulate. A row-major frag {a0..a3}, B col-major {b0,b1}.
__device__ __forceinline__ void mma8(float acc[4], float4 a, float2 b) {
    uint32_t A0 = __float_as_uint(a.x), A1 = __float_as_uint(a.y);
    uint32_t A2 = __float_as_uint(a.z), A3 = __float_as_uint(a.w);
    uint32_t B0 = __float_as_uint(b.x), B1 = __float_as_uint(b.y);
    asm volatile(
        "mma.sync.aligned.m16n8k8.row.col.f32.tf32.tf32.f32 "
        "{%0,%1,%2,%3}, {%4,%5,%6,%7}, {%8,%9}, {%0,%1,%2,%3};\n"
        : "+f"(acc[0]), "+f"(acc[1]), "+f"(acc[2]), "+f"(acc[3])
        : "r"(A0), "r"(A1), "r"(A2), "r"(A3), "r"(B0), "r"(B1));
}

// ---------------- RoPE table ------------------------------------------------
__global__ void rope_tab_kernel() {
    int l = blockIdx.x;
    int j = threadIdx.x;
    float inv_f = (float)pow(10000.0, -(double)j / 32.0);
    float ang_f = (float)l * inv_f;
    double a = (double)ang_f;
    g_cos[l * 32 + j] = (float)cos(a);
    g_sin[l * 32 + j] = (float)sin(a);
}

// ---------------- LN1: one block per row, 256 threads ----------------------
__global__ void __launch_bounds__(256) ln1_kernel(const float* __restrict__ x,
                                                  const float* __restrict__ w,
                                                  const float* __restrict__ b) {
    __shared__ float sa[8], sb[8];
    int row = blockIdx.x;
    int t = threadIdx.x;
    const float4* xr = (const float4*)(x + (size_t)row * D_);
    float4 v = xr[t];
    float s  = v.x + v.y + v.z + v.w;
    float ss = v.x * v.x + v.y * v.y + v.z * v.z + v.w * v.w;
#pragma unroll
    for (int o = 16; o > 0; o >>= 1) {
        s  += __shfl_xor_sync(0xffffffffu, s, o);
        ss += __shfl_xor_sync(0xffffffffu, ss, o);
    }
    if ((t & 31) == 0) { sa[t >> 5] = s; sb[t >> 5] = ss; }
    __syncthreads();
    float ts = 0.f, tss = 0.f;
#pragma unroll
    for (int i = 0; i < 8; i++) { ts += sa[i]; tss += sb[i]; }
    float mu  = ts * (1.0f / D_);
    float var = tss * (1.0f / D_) - mu * mu;
    float rs  = rsqrtf(var + 1e-5f);
    float4 wv = ((const float4*)w)[t];
    float4 bv = ((const float4*)b)[t];
    float4 o;
    o.x = (v.x - mu) * rs * wv.x + bv.x;
    o.y = (v.y - mu) * rs * wv.y + bv.y;
    o.z = (v.z - mu) * rs * wv.z + bv.z;
    o.w = (v.w - mu) * rs * wv.w + bv.w;
    ((float4*)(g_h + (size_t)row * D_))[t] = o;
}

// ---------------- q/k LayerNorm + RoPE (in place on g_qkv) -----------------
__global__ void __launch_bounds__(256) qkln_rope_kernel(const float* __restrict__ qw,
                                                        const float* __restrict__ kw) {
    __shared__ float sa[8], sb[8];
    __shared__ float sv[D_];
    int row   = blockIdx.x;
    int which = blockIdx.y;
    int t = threadIdx.x;
    float* base = g_qkv + (size_t)row * D3_ + which * D_;
    const float* w = which ? kw : qw;

    float4 v = ((const float4*)base)[t];
    float s  = v.x + v.y + v.z + v.w;
    float ss = v.x * v.x + v.y * v.y + v.z * v.z + v.w * v.w;
#pragma unroll
    for (int o = 16; o > 0; o >>= 1) {
        s  += __shfl_xor_sync(0xffffffffu, s, o);
        ss += __shfl_xor_sync(0xffffffffu, ss, o);
    }
    if ((t & 31) == 0) { sa[t >> 5] = s; sb[t >> 5] = ss; }
    __syncthreads();
    float ts = 0.f, tss = 0.f;
#pragma unroll
    for (int i = 0; i < 8; i++) { ts += sa[i]; tss += sb[i]; }
    float mu  = ts * (1.0f / D_);
    float var = tss * (1.0f / D_) - mu * mu;
    float rs  = rsqrtf(var + 1e-5f);
    float4 wv = ((const float4*)w)[t];
    sv[4 * t + 0] = (v.x - mu) * rs * wv.x;
    sv[4 * t + 1] = (v.y - mu) * rs * wv.y;
    sv[4 * t + 2] = (v.z - mu) * rs * wv.z;
    sv[4 * t + 3] = (v.w - mu) * rs * wv.w;
    __syncthreads();

    int l = row & (L_ - 1);
#pragma unroll
    for (int c = 0; c < 4; c++) {
        int col = 4 * t + c;
        int d   = col & 63;
        int dd  = d & 31;
        float cs = g_cos[l * 32 + dd];
        float sn = g_sin[l * 32 + dd];
        float y = sv[col];
        float res;
        if (d < 32) res = y * cs - sv[col + 32] * sn;
        else        res = y * cs + sv[col - 32] * sn;
        base[col] = res;
    }
}

// ---------------- TF32x3 tensor-core GEMM: 128x128 tile, kchunk 16 ---------
// smem (dynamic): Aph[2][2048] Apl[2][2048] Bph[2][2048] Bpl[2][2048] = 64KB
__device__ __forceinline__ void gemm_ldg(const float* __restrict__ A,
                                         const float* __restrict__ Bm,
                                         int N, int K, int m0, int n0, int kt,
                                         int tid, float4 va[2], float4 vb[2]) {
#pragma unroll
    for (int j = 0; j < 2; j++) {
        int id = tid * 2 + j;
        int r = id >> 2, c = (id & 3) * 4;
        va[j] = *(const float4*)(A + (size_t)(m0 + r) * K + kt + c);
        int k = id >> 5, n = (id & 31) * 4;
        vb[j] = *(const float4*)(Bm + (size_t)(kt + k) * N + n0 + n);
    }
}

__device__ __forceinline__ void gemm_sts(float* Aph, float* Apl,
                                         float* Bph, float* Bpl, int tid,
                                         const float4 va[2], const float4 vb[2]) {
#pragma unroll
    for (int j = 0; j < 2; j++) {
        int id = tid * 2 + j;
        {
            int r = id >> 2, c = (id & 3) * 4;
            const float* f = (const float*)&va[j];
#pragma unroll
            for (int cc = 0; cc < 4; cc++) {
                int cp = c + cc;
                int idx = (((r >> 4) * 2 + (cp >> 3)) << 7)
                        + (((r & 7) << 2) + (cp & 3)) * 4
                        + ((r >> 3) & 1) + (((cp >> 2) & 1) << 1);
                float v = f[cc];
                float hv = to_tf32(v);
                Aph[idx] = hv;
                Apl[idx] = to_tf32(v - hv);
            }
        }
        {
            int k = id >> 5, n = (id & 31) * 4;
            const float* f = (const float*)&vb[j];
#pragma unroll
            for (int cc = 0; cc < 4; cc++) {
                int np = n + cc;
                int idx = (((k >> 3) * 16 + (np >> 3)) << 6)
                        + (((np & 7) << 2) + (k & 3)) * 2 + ((k >> 2) & 1);
                float v = f[cc];
                float hv = to_tf32(v);
                Bph[idx] = hv;
                Bpl[idx] = to_tf32(v - hv);
            }
        }
    }
}

__device__ __forceinline__ void sgemm_tc_body(const float* __restrict__ A,
                                              const float* __restrict__ Bm,
                                              float* __restrict__ C,
                                              int N, int K) {
    extern __shared__ float smg[];
    float* Aph = smg;            // [2][2048]
    float* Apl = smg + 4096;
    float* Bph = smg + 8192;
    float* Bpl = smg + 12288;

    int tid = threadIdx.x, wid = tid >> 5, lane = tid & 31;
    int warp_m = wid >> 1, warp_n = wid & 1;
    int m0 = blockIdx.y * 128, n0 = blockIdx.x * 128;

    float acc[2][8][4] = {};
    float4 va[2], vb[2];
    gemm_ldg(A, Bm, N, K, m0, n0, 0, tid, va, vb);
    gemm_sts(Aph, Apl, Bph, Bpl, tid, va, vb);

    int nch = K / 16;
    for (int c = 0; c < nch; c++) {
        if (c + 1 < nch) gemm_ldg(A, Bm, N, K, m0, n0, (c + 1) * 16, tid, va, vb);
        __syncthreads();
        int buf = (c & 1) * 2048;
        const float* aph = Aph + buf;
        const float* apl = Apl + buf;
        const float* bph = Bph + buf;
        const float* bpl = Bpl + buf;
#pragma unroll
        for (int ks = 0; ks < 2; ks++) {
            float4 a0h = *(const float4*)&aph[(((warp_m * 2 + 0) * 2 + ks) << 7) + lane * 4];
            float4 a0l = *(const float4*)&apl[(((warp_m * 2 + 0) * 2 + ks) << 7) + lane * 4];
            float4 a1h = *(const float4*)&aph[(((warp_m * 2 + 1) * 2 + ks) << 7) + lane * 4];
            float4 a1l = *(const float4*)&apl[(((warp_m * 2 + 1) * 2 + ks) << 7) + lane * 4];
#pragma unroll
            for (int nt = 0; nt < 8; nt++) {
                int bo = ((ks * 16 + warp_n * 8 + nt) << 6) + lane * 2;
                float2 bh = *(const float2*)&bph[bo];
                float2 bl = *(const float2*)&bpl[bo];
                mma8(acc[0][nt], a0h, bh);
                mma8(acc[0][nt], a0l, bh);
                mma8(acc[0][nt], a0h, bl);
                mma8(acc[1][nt], a1h, bh);
                mma8(acc[1][nt], a1l, bh);
                mma8(acc[1][nt], a1h, bl);
            }
        }
        if (c + 1 < nch) {
            int nb = ((c + 1) & 1) * 2048;
            gemm_sts(Aph + nb, Apl + nb, Bph + nb, Bpl + nb, tid, va, vb);
        }
    }
    // epilogue
#pragma unroll
    for (int mt = 0; mt < 2; mt++) {
        int r0 = m0 + warp_m * 32 + mt * 16 + (lane >> 2);
        int cc = n0 + warp_n * 64 + (lane & 3) * 2;
#pragma unroll
        for (int nt = 0; nt < 8; nt++) {
            *(float2*)(C + (size_t)r0 * N + cc + nt * 8) =
                make_float2(acc[mt][nt][0], acc[mt][nt][1]);
            *(float2*)(C + (size_t)(r0 + 8) * N + cc + nt * 8) =
                make_float2(acc[mt][nt][2], acc[mt][nt][3]);
        }
    }
}

__global__ void __launch_bounds__(256) gemm_qkv_kernel(const float* __restrict__ W) {
    sgemm_tc_body(g_h, W, g_qkv, D3_, D_);
}
__global__ void __launch_bounds__(256) gemm_out_kernel(const float* __restrict__ W,
                                                       float* __restrict__ out) {
    sgemm_tc_body(g_ctx, W, out, D_, D_);
}

// ---------------- flash attention, tf32x3, 128q x 64k tiles, 256 threads ---
// smem floats: Qh 8192 | Ql 8192 | Kh 4096 | Kl 4096 | Vh 4096 | Vl 4096 |
//              Ph 8192 | Pl 8192 | kseq 64 ints      = 196864 B
#define ATTN_SMEM (49152 * 4 + 256)

__global__ void __launch_bounds__(256) attn_tc_kernel(const int* __restrict__ seq_id) {
    extern __shared__ float smA[];
    float* Qh = smA;
    float* Ql = smA + 8192;
    float* Kh = smA + 16384;
    float* Kl = smA + 20480;
    float* Vh = smA + 24576;
    float* Vl = smA + 28672;
    float* Ph = smA + 32768;
    float* Pl = smA + 40960;
    int*  kseq = (int*)(smA + 49152);

    int qt = blockIdx.x, h = blockIdx.y, b = blockIdx.z;
    int tid = threadIdx.x, wid = tid >> 5, lane = tid & 31;
    int q0 = qt * 128;
    size_t rowOff = (size_t)b * L_;
    const float* qbase = g_qkv + (rowOff + q0) * D3_ + h * DH_;

    // pack Q tile (128 x 64) into A-frag layout, hi/lo
    for (int e = tid; e < 8192; e += 256) {
        int q = e >> 6, d = e & 63;
        float v = qbase[(size_t)q * D3_ + d];
        float hv = to_tf32(v);
        int idx = ((q >> 4) * 8 + (d >> 3)) * 128 + (((q & 7) << 2) + (d & 3)) * 4
                + ((q >> 3) & 1) + (((d >> 2) & 1) << 1);
        Qh[idx] = hv;
        Ql[idx] = to_tf32(v - hv);
    }
    int qs0 = seq_id[b * L_ + q0 + wid * 16 + (lane >> 2)];
    int qs1 = seq_id[b * L_ + q0 + wid * 16 + (lane >> 2) + 8];

    float O[8][4] = {};
    float m0v = -1e30f, m1v = -1e30f, l0 = 0.f, l1 = 0.f;

    int c0 = (lane & 3) * 2;
    int lA = (lane >> 2) * 4 + (c0 & 3);
    int rA = ((c0 >> 2) & 1) << 1;
    int lB = (lane >> 2) * 4 + ((c0 + 1) & 3);
    int rB = (((c0 + 1) >> 2) & 1) << 1;

    for (int kt = 0; kt < L_ / 64; kt++) {
        __syncthreads();   // all warps done with prev K/V (and Q stores on iter 0)
        const float* kbase = g_qkv + (rowOff + kt * 64) * D3_ + D_ + h * DH_;
        const float* vbase = kbase + D_;
        for (int e = tid; e < 4096; e += 256) {
            int kp = e >> 6, d = e & 63;
            float kv = kbase[(size_t)kp * D3_ + d];
            float kh = to_tf32(kv);
            int kidx = ((d >> 3) * 8 + (kp >> 3)) * 64 + ((kp & 7) * 4 + (d & 3)) * 2
                     + ((d >> 2) & 1);
            Kh[kidx] = kh;
            Kl[kidx] = to_tf32(kv - kh);
            float vv = vbase[(size_t)kp * D3_ + d];
            float vh = to_tf32(vv);
            int vidx = ((kp >> 3) * 8 + (d >> 3)) * 64 + ((d & 7) * 4 + (kp & 3)) * 2
                     + ((kp >> 2) & 1);
            Vh[vidx] = vh;
            Vl[vidx] = to_tf32(vv - vh);
        }
        if (tid < 64) kseq[tid] = seq_id[b * L_ + kt * 64 + tid];
        __syncthreads();

        // S = Q K^T  (3-term tf32)
        float S[8][4] = {};
#pragma unroll
        for (int ks = 0; ks < 8; ks++) {
            float4 ah = *(const float4*)&Qh[(wid * 8 + ks) * 128 + lane * 4];
            float4 al = *(const float4*)&Ql[(wid * 8 + ks) * 128 + lane * 4];
#pragma unroll
            for (int nt = 0; nt < 8; nt++) {
                float2 bh = *(const float2*)&Kh[(ks * 8 + nt) * 64 + lane * 2];
                float2 bl = *(const float2*)&Kl[(ks * 8 + nt) * 64 + lane * 2];
                mma8(S[nt], ah, bh);
                mma8(S[nt], al, bh);
                mma8(S[nt], ah, bl);
            }
        }
        // mask + scale + row max
        float mx0 = -1e30f, mx1 = -1e30f;
#pragma unroll
        for (int nt = 0; nt < 8; nt++) {
            int k0 = kseq[nt * 8 + c0], k1 = kseq[nt * 8 + c0 + 1];
            S[nt][0] = (qs0 == k0) ? S[nt][0] * 0.125f : -1e30f;
            S[nt][1] = (qs0 == k1) ? S[nt][1] * 0.125f : -1e30f;
            S[nt][2] = (qs1 == k0) ? S[nt][2] * 0.125f : -1e30f;
            S[nt][3] = (qs1 == k1) ? S[nt][3] * 0.125f : -1e30f;
            mx0 = fmaxf(mx0, fmaxf(S[nt][0], S[nt][1]));
            mx1 = fmaxf(mx1, fmaxf(S[nt][2], S[nt][3]));
        }
        mx0 = fmaxf(mx0, __shfl_xor_sync(0xffffffffu, mx0, 1));
        mx0 = fmaxf(mx0, __shfl_xor_sync(0xffffffffu, mx0, 2));
        mx1 = fmaxf(mx1, __shfl_xor_sync(0xffffffffu, mx1, 1));
        mx1 = fmaxf(mx1, __shfl_xor_sync(0xffffffffu, mx1, 2));
        float mn0 = fmaxf(m0v, mx0), mn1 = fmaxf(m1v, mx1);
        float al0 = __expf(m0v - mn0), al1 = __expf(m1v - mn1);
        m0v = mn0; m1v = mn1;

        float rs0 = 0.f, rs1 = 0.f;
#pragma unroll
        for (int nt = 0; nt < 8; nt++) {
            float p00 = (S[nt][0] <= -9e29f) ? 0.f : __expf(S[nt][0] - mn0);
            float p01 = (S[nt][1] <= -9e29f) ? 0.f : __expf(S[nt][1] - mn0);
            float p10 = (S[nt][2] <= -9e29f) ? 0.f : __expf(S[nt][2] - mn1);
            float p11 = (S[nt][3] <= -9e29f) ? 0.f : __expf(S[nt][3] - mn1);
            rs0 += p00 + p01;
            rs1 += p10 + p11;
            float* pbh = &Ph[(wid * 8 + nt) * 128];
            float* pbl = &Pl[(wid * 8 + nt) * 128];
            float h00 = to_tf32(p00), h01 = to_tf32(p01);
            float h10 = to_tf32(p10), h11 = to_tf32(p11);
            pbh[lA * 4 + rA]     = h00;  pbl[lA * 4 + rA]     = to_tf32(p00 - h00);
            pbh[lB * 4 + rB]     = h01;  pbl[lB * 4 + rB]     = to_tf32(p01 - h01);
            pbh[lA * 4 + rA + 1] = h10;  pbl[lA * 4 + rA + 1] = to_tf32(p10 - h10);
            pbh[lB * 4 + rB + 1] = h11;  pbl[lB * 4 + rB + 1] = to_tf32(p11 - h11);
        }
        rs0 += __shfl_xor_sync(0xffffffffu, rs0, 1);
        rs0 += __shfl_xor_sync(0xffffffffu, rs0, 2);
        rs1 += __shfl_xor_sync(0xffffffffu, rs1, 1);
        rs1 += __shfl_xor_sync(0xffffffffu, rs1, 2);
        l0 = l0 * al0 + rs0;
        l1 = l1 * al1 + rs1;
#pragma unroll
        for (int nt = 0; nt < 8; nt++) {
            O[nt][0] *= al0; O[nt][1] *= al0;
            O[nt][2] *= al1; O[nt][3] *= al1;
        }
        __syncwarp();   // P region is per-warp; cross-lane visibility only
        // O += P V (3-term tf32)
#pragma unroll
        for (int ks = 0; ks < 8; ks++) {
            float4 ah = *(const float4*)&Ph[(wid * 8 + ks) * 128 + lane * 4];
            float4 al = *(const float4*)&Pl[(wid * 8 + ks) * 128 + lane * 4];
#pragma unroll
            for (int nt = 0; nt < 8; nt++) {
                float2 bh = *(const float2*)&Vh[(ks * 8 + nt) * 64 + lane * 2];
                float2 bl = *(const float2*)&Vl[(ks * 8 + nt) * 64 + lane * 2];
                mma8(O[nt], ah, bh);
                mma8(O[nt], al, bh);
                mma8(O[nt], ah, bl);
            }
        }
    }
    // epilogue
    float inv0 = 1.0f / l0, inv1 = 1.0f / l1;
    int r0 = q0 + wid * 16 + (lane >> 2);
    float* obase = g_ctx + (rowOff + r0) * D_ + h * DH_ + (lane & 3) * 2;
#pragma unroll
    for (int nt = 0; nt < 8; nt++) {
        *(float2*)(obase + nt * 8) =
            make_float2(O[nt][0] * inv0, O[nt][1] * inv0);
        *(float2*)(obase + (size_t)8 * D_ + nt * 8) =
            make_float2(O[nt][2] * inv1, O[nt][3] * inv1);
    }
}

// ---------------- launch ----------------------------------------------------
extern "C" void kernel_launch(void* const* d_in, const int* in_sizes, int n_in,
                              void* d_out, int out_size) {
    const float* x    = (const float*)d_in[0];
    const int*   seq  = (const int*)d_in[1];
    const float* ln1w = (const float*)d_in[2];
    const float* ln1b = (const float*)d_in[3];
    const float* wqkv = (const float*)d_in[4];
    const float* qlnw = (const float*)d_in[5];
    const float* klnw = (const float*)d_in[6];
    const float* wout = (const float*)d_in[7];
    float* out = (float*)d_out;

    const int gemm_smem = 16384 * 4;   // 64 KB
    cudaFuncSetAttribute(gemm_qkv_kernel,
                         cudaFuncAttributeMaxDynamicSharedMemorySize, gemm_smem);
    cudaFuncSetAttribute(gemm_out_kernel,
                         cudaFuncAttributeMaxDynamicSharedMemorySize, gemm_smem);
    cudaFuncSetAttribute(attn_tc_kernel,
                         cudaFuncAttributeMaxDynamicSharedMemorySize, ATTN_SMEM);

    rope_tab_kernel<<<L_, 32>>>();
    ln1_kernel<<<R_, 256>>>(x, ln1w, ln1b);
    gemm_qkv_kernel<<<dim3(D3_ / 128, R_ / 128), 256, gemm_smem>>>(wqkv);
    qkln_rope_kernel<<<dim3(R_, 2), 256>>>(qlnw, klnw);
    attn_tc_kernel<<<dim3(L_ / 128, H_, B_), 256, ATTN_SMEM>>>(seq);
    gemm_out_kernel<<<dim3(D_ / 128, R_ / 128), 256, gemm_smem>>>(wout, out);
}

// round 5
// speedup vs baseline: 4.1682x; 4.1682x over previous
#include <cuda_runtime.h>
#include <cuda_bf16.h>
#include <math.h>
#include <stdint.h>

#define B_  2
#define L_  2048
#define D_  1024
#define H_  16
#define DH_ 64
#define R_  (B_ * L_)
#define D3_ (3 * D_)

// ---------------- scratch ----------------------------------------------------
__device__ float g_h[(size_t)R_ * D_];
__device__ float g_qkv[(size_t)R_ * D3_];
__device__ float g_ctx[(size_t)R_ * D_];
__device__ float g_cos[L_ * 32];
__device__ float g_sin[L_ * 32];

// ---------------- helpers ----------------------------------------------------
__device__ __forceinline__ uint32_t pk(float a, float b) {
    __nv_bfloat162 t = __floats2bfloat162_rn(a, b);
    return *reinterpret_cast<uint32_t*>(&t);
}
__device__ __forceinline__ void hl(float x, float& h, float& l) {
    h = __bfloat162float(__float2bfloat16(x));
    l = x - h;
}
// float4 -> packed bf16 hi pair / lo pair
__device__ __forceinline__ void cvt4(float4 v, uint32_t& h01, uint32_t& h23,
                                     uint32_t& l01, uint32_t& l23) {
    float hx, lx, hy, ly, hz, lz, hw, lw;
    hl(v.x, hx, lx); hl(v.y, hy, ly); hl(v.z, hz, lz); hl(v.w, hw, lw);
    h01 = pk(hx, hy); h23 = pk(hz, hw);
    l01 = pk(lx, ly); l23 = pk(lz, lw);
}

__device__ __forceinline__ void ldsm4(uint32_t a, uint32_t& r0, uint32_t& r1,
                                      uint32_t& r2, uint32_t& r3) {
    asm volatile("ldmatrix.sync.aligned.m8n8.x4.shared.b16 {%0,%1,%2,%3},[%4];"
                 : "=r"(r0), "=r"(r1), "=r"(r2), "=r"(r3) : "r"(a));
}
__device__ __forceinline__ void ldsm4t(uint32_t a, uint32_t& r0, uint32_t& r1,
                                       uint32_t& r2, uint32_t& r3) {
    asm volatile("ldmatrix.sync.aligned.m8n8.x4.trans.shared.b16 {%0,%1,%2,%3},[%4];"
                 : "=r"(r0), "=r"(r1), "=r"(r2), "=r"(r3) : "r"(a));
}
__device__ __forceinline__ void mma16(float* acc, const uint32_t* a,
                                      uint32_t b0, uint32_t b1) {
    asm volatile(
        "mma.sync.aligned.m16n8k16.row.col.f32.bf16.bf16.f32 "
        "{%0,%1,%2,%3},{%4,%5,%6,%7},{%8,%9},{%0,%1,%2,%3};"
        : "+f"(acc[0]), "+f"(acc[1]), "+f"(acc[2]), "+f"(acc[3])
        : "r"(a[0]), "r"(a[1]), "r"(a[2]), "r"(a[3]), "r"(b0), "r"(b1));
}

// ---------------- RoPE table -------------------------------------------------
__global__ void rope_tab_kernel() {
    int l = blockIdx.x;
    int j = threadIdx.x;
    float inv_f = (float)pow(10000.0, -(double)j / 32.0);
    float ang_f = (float)l * inv_f;
    double a = (double)ang_f;
    g_cos[l * 32 + j] = (float)cos(a);
    g_sin[l * 32 + j] = (float)sin(a);
}

// ---------------- LN1 --------------------------------------------------------
__global__ void __launch_bounds__(256) ln1_kernel(const float* __restrict__ x,
                                                  const float* __restrict__ w,
                                                  const float* __restrict__ b) {
    __shared__ float sa[8], sb[8];
    int row = blockIdx.x;
    int t = threadIdx.x;
    float4 v = ((const float4*)(x + (size_t)row * D_))[t];
    float s  = v.x + v.y + v.z + v.w;
    float ss = v.x * v.x + v.y * v.y + v.z * v.z + v.w * v.w;
#pragma unroll
    for (int o = 16; o > 0; o >>= 1) {
        s  += __shfl_xor_sync(0xffffffffu, s, o);
        ss += __shfl_xor_sync(0xffffffffu, ss, o);
    }
    if ((t & 31) == 0) { sa[t >> 5] = s; sb[t >> 5] = ss; }
    __syncthreads();
    float ts = 0.f, tss = 0.f;
#pragma unroll
    for (int i = 0; i < 8; i++) { ts += sa[i]; tss += sb[i]; }
    float mu  = ts * (1.0f / D_);
    float var = tss * (1.0f / D_) - mu * mu;
    float rs  = rsqrtf(var + 1e-5f);
    float4 wv = ((const float4*)w)[t];
    float4 bv = ((const float4*)b)[t];
    float4 o;
    o.x = (v.x - mu) * rs * wv.x + bv.x;
    o.y = (v.y - mu) * rs * wv.y + bv.y;
    o.z = (v.z - mu) * rs * wv.z + bv.z;
    o.w = (v.w - mu) * rs * wv.w + bv.w;
    ((float4*)(g_h + (size_t)row * D_))[t] = o;
}

// ---------------- q/k LN + RoPE ----------------------------------------------
__global__ void __launch_bounds__(256) qkln_rope_kernel(const float* __restrict__ qw,
                                                        const float* __restrict__ kw) {
    __shared__ float sa[8], sb[8];
    __shared__ float sv[D_];
    int row = blockIdx.x;
    int which = blockIdx.y;
    int t = threadIdx.x;
    float* base = g_qkv + (size_t)row * D3_ + which * D_;
    const float* w = which ? kw : qw;

    float4 v = ((const float4*)base)[t];
    float s  = v.x + v.y + v.z + v.w;
    float ss = v.x * v.x + v.y * v.y + v.z * v.z + v.w * v.w;
#pragma unroll
    for (int o = 16; o > 0; o >>= 1) {
        s  += __shfl_xor_sync(0xffffffffu, s, o);
        ss += __shfl_xor_sync(0xffffffffu, ss, o);
    }
    if ((t & 31) == 0) { sa[t >> 5] = s; sb[t >> 5] = ss; }
    __syncthreads();
    float ts = 0.f, tss = 0.f;
#pragma unroll
    for (int i = 0; i < 8; i++) { ts += sa[i]; tss += sb[i]; }
    float mu  = ts * (1.0f / D_);
    float var = tss * (1.0f / D_) - mu * mu;
    float rs  = rsqrtf(var + 1e-5f);
    float4 wv = ((const float4*)w)[t];
    sv[4 * t + 0] = (v.x - mu) * rs * wv.x;
    sv[4 * t + 1] = (v.y - mu) * rs * wv.y;
    sv[4 * t + 2] = (v.z - mu) * rs * wv.z;
    sv[4 * t + 3] = (v.w - mu) * rs * wv.w;
    __syncthreads();

    int l = row & (L_ - 1);
#pragma unroll
    for (int c = 0; c < 4; c++) {
        int col = 4 * t + c;
        int d = col & 63, dd = d & 31;
        float cs = g_cos[l * 32 + dd];
        float sn = g_sin[l * 32 + dd];
        float y = sv[col];
        base[col] = (d < 32) ? (y * cs - sv[col + 32] * sn)
                             : (y * cs + sv[col - 32] * sn);
    }
}

// ---------------- bf16x2 GEMM: 128x128 tile, BK=16, 256 thr -------------------
#define GP_A 80    // A row: hi 32B | lo 32B | pad 16B
#define GP_B 512   // B k-row: hi 256B | lo 256B (swizzled)
#define ABUF (128 * GP_A)
#define BBUF (16 * GP_B)

__device__ __forceinline__ void g_ldg(const float* __restrict__ A,
                                      const float* __restrict__ W,
                                      int N, int K, int m0, int n0, int kt,
                                      int tid, float4 va[2], float4 vb[2]) {
#pragma unroll
    for (int j = 0; j < 2; j++) {
        int id = tid * 2 + j;
        int m = id >> 2, kq = (id & 3) * 4;
        va[j] = *(const float4*)(A + (size_t)(m0 + m) * K + kt + kq);
        int k = id >> 5, n = (id & 31) * 4;
        vb[j] = *(const float4*)(W + (size_t)(kt + k) * N + n0 + n);
    }
}
__device__ __forceinline__ void g_sts(char* Asm, char* Bsm, int tid,
                                      const float4 va[2], const float4 vb[2]) {
#pragma unroll
    for (int j = 0; j < 2; j++) {
        int id = tid * 2 + j;
        {
            int m = id >> 2, kq = (id & 3) * 4;
            uint32_t h01, h23, l01, l23;
            cvt4(va[j], h01, h23, l01, l23);
            char* p = Asm + m * GP_A + kq * 2;
            *(uint2*)p        = make_uint2(h01, h23);
            *(uint2*)(p + 32) = make_uint2(l01, l23);
        }
        {
            int k = id >> 5, n = (id & 31) * 4;
            uint32_t h01, h23, l01, l23;
            cvt4(vb[j], h01, h23, l01, l23);
            int sw = (n * 2) ^ ((k & 7) << 4);
            char* p = Bsm + k * GP_B;
            *(uint2*)(p + sw)       = make_uint2(h01, h23);
            *(uint2*)(p + 256 + sw) = make_uint2(l01, l23);
        }
    }
}

__device__ __forceinline__ void gemm_body(const float* __restrict__ A,
                                          const float* __restrict__ W,
                                          float* __restrict__ C, int N, int K) {
    __shared__ __align__(16) char sm[2 * ABUF + 2 * BBUF];   // 36864 B
    char* Asm = sm;
    char* Bsm = sm + 2 * ABUF;
    int tid = threadIdx.x, wid = tid >> 5, lane = tid & 31;
    int wm = wid >> 1, wn = wid & 1;
    int m0 = blockIdx.y * 128, n0 = blockIdx.x * 128;
    uint32_t aBase = (uint32_t)__cvta_generic_to_shared(Asm);
    uint32_t bBase = (uint32_t)__cvta_generic_to_shared(Bsm);

    float acc[2][8][4] = {};
    float4 va[2], vb[2];
    g_ldg(A, W, N, K, m0, n0, 0, tid, va, vb);
    g_sts(Asm, Bsm, tid, va, vb);

    int nch = K / 16;
    for (int c = 0; c < nch; c++) {
        if (c + 1 < nch) g_ldg(A, W, N, K, m0, n0, (c + 1) * 16, tid, va, vb);
        __syncthreads();
        uint32_t aB = aBase + (c & 1) * ABUF;
        uint32_t bB = bBase + (c & 1) * BBUF;

        uint32_t ah[2][4], al[2][4];
#pragma unroll
        for (int mt = 0; mt < 2; mt++) {
            int row = wm * 32 + mt * 16 + (lane & 15);
            uint32_t ad = aB + row * GP_A + (lane >> 4) * 16;
            ldsm4(ad, ah[mt][0], ah[mt][1], ah[mt][2], ah[mt][3]);
            ldsm4(ad + 32, al[mt][0], al[mt][1], al[mt][2], al[mt][3]);
        }
#pragma unroll
        for (int np = 0; np < 4; np++) {
            int k = lane & 15;
            int ntile = wn * 8 + np * 2 + (lane >> 4);
            uint32_t bd = bB + k * GP_B + ((ntile * 16) ^ ((k & 7) << 4));
            uint32_t bh0, bh1, bh2, bh3, bl0, bl1, bl2, bl3;
            ldsm4t(bd, bh0, bh1, bh2, bh3);
            ldsm4t(bd + 256, bl0, bl1, bl2, bl3);
#pragma unroll
            for (int mt = 0; mt < 2; mt++) {
                mma16(acc[mt][np * 2],     ah[mt], bh0, bh1);
                mma16(acc[mt][np * 2],     al[mt], bh0, bh1);
                mma16(acc[mt][np * 2],     ah[mt], bl0, bl1);
                mma16(acc[mt][np * 2 + 1], ah[mt], bh2, bh3);
                mma16(acc[mt][np * 2 + 1], al[mt], bh2, bh3);
                mma16(acc[mt][np * 2 + 1], ah[mt], bl2, bl3);
            }
        }
        if (c + 1 < nch)
            g_sts(Asm + ((c + 1) & 1) * ABUF, Bsm + ((c + 1) & 1) * BBUF, tid, va, vb);
    }
#pragma unroll
    for (int mt = 0; mt < 2; mt++) {
        int r = m0 + wm * 32 + mt * 16 + (lane >> 2);
        int cc = n0 + wn * 64 + (lane & 3) * 2;
#pragma unroll
        for (int nt = 0; nt < 8; nt++) {
            *(float2*)(C + (size_t)r * N + cc + nt * 8) =
                make_float2(acc[mt][nt][0], acc[mt][nt][1]);
            *(float2*)(C + (size_t)(r + 8) * N + cc + nt * 8) =
                make_float2(acc[mt][nt][2], acc[mt][nt][3]);
        }
    }
}

__global__ void __launch_bounds__(256) gemm_qkv_kernel(const float* __restrict__ W) {
    gemm_body(g_h, W, g_qkv, D3_, D_);
}
__global__ void __launch_bounds__(256) gemm_out_kernel(const float* __restrict__ W,
                                                       float* __restrict__ out) {
    gemm_body(g_ctx, W, out, D_, D_);
}

// ---------------- flash attention: bf16x2, 128q x 64k, 256 thr ---------------
// smem bytes: Q 32768 | K 16384 | V 16384 | P 32768 | kseq 256 = 98560
#define SM_Q 0
#define SM_K 32768
#define SM_V 49152
#define SM_P 65536
#define SM_SEQ 98304
#define ATTN_SMEM 98560

__global__ void __launch_bounds__(256) attn_kernel(const int* __restrict__ seq_id) {
    extern __shared__ __align__(16) char smA[];
    char* Qs = smA + SM_Q;
    char* Ks = smA + SM_K;
    char* Vs = smA + SM_V;
    char* Ps = smA + SM_P;
    int* kseq = (int*)(smA + SM_SEQ);
    uint32_t qB = (uint32_t)__cvta_generic_to_shared(Qs);
    uint32_t kB = (uint32_t)__cvta_generic_to_shared(Ks);
    uint32_t vB = (uint32_t)__cvta_generic_to_shared(Vs);
    uint32_t pB = (uint32_t)__cvta_generic_to_shared(Ps);

    int qt = blockIdx.x, h = blockIdx.y, b = blockIdx.z;
    int tid = threadIdx.x, wid = tid >> 5, lane = tid & 31;
    int q0 = qt * 128;
    size_t rowOff = (size_t)b * L_;
    const float* qbase = g_qkv + (rowOff + q0) * D3_ + h * DH_;
    const int* seqb = seq_id + b * L_;

    // load Q tile (128 x 64) as bf16 hi/lo, row-major, XOR-swizzled
#pragma unroll
    for (int t = 0; t < 8; t++) {
        int id = tid + t * 256;          // 0..2047
        int q = id >> 4, dq = (id & 15) * 4;
        float4 v = *(const float4*)(qbase + (size_t)q * D3_ + dq);
        uint32_t h01, h23, l01, l23;
        cvt4(v, h01, h23, l01, l23);
        int sw = (dq * 2) ^ ((q & 7) << 4);
        char* p = Qs + q * 256 + sw;
        *(uint2*)p         = make_uint2(h01, h23);
        *(uint2*)(p + 128) = make_uint2(l01, l23);
    }
    int qs0 = seqb[q0 + wid * 16 + (lane >> 2)];
    int qs1 = seqb[q0 + wid * 16 + (lane >> 2) + 8];

    // valid key range (seq_id is sorted): [klo, khi)
    int sa = seqb[q0], sb = seqb[q0 + 127];
    int lo = 0, hi = L_;
    while (lo < hi) { int mid = (lo + hi) >> 1; if (seqb[mid] < sa) lo = mid + 1; else hi = mid; }
    int klo = lo;
    lo = 0; hi = L_;
    while (lo < hi) { int mid = (lo + hi) >> 1; if (seqb[mid] <= sb) lo = mid + 1; else hi = mid; }
    int khi = lo;
    int kt0 = klo >> 6, kt1 = (khi - 1) >> 6;

    float O[8][4] = {};
    float m0v = -1e30f, m1v = -1e30f, l0s = 0.f, l1s = 0.f;
    int c0 = (lane & 3) * 2;

    for (int kt = kt0; kt <= kt1; kt++) {
        __syncthreads();
        const float* kbase = g_qkv + (rowOff + kt * 64) * D3_ + D_ + h * DH_;
        const float* vbase = kbase + D_;
#pragma unroll
        for (int t = 0; t < 4; t++) {
            int id = tid + t * 256;      // 0..1023
            int kp = id >> 4, dq = (id & 15) * 4;
            int sw = (dq * 2) ^ ((kp & 7) << 4);
            {
                float4 v = *(const float4*)(kbase + (size_t)kp * D3_ + dq);
                uint32_t h01, h23, l01, l23;
                cvt4(v, h01, h23, l01, l23);
                char* p = Ks + kp * 256 + sw;
                *(uint2*)p         = make_uint2(h01, h23);
                *(uint2*)(p + 128) = make_uint2(l01, l23);
            }
            {
                float4 v = *(const float4*)(vbase + (size_t)kp * D3_ + dq);
                uint32_t h01, h23, l01, l23;
                cvt4(v, h01, h23, l01, l23);
                char* p = Vs + kp * 256 + sw;
                *(uint2*)p         = make_uint2(h01, h23);
                *(uint2*)(p + 128) = make_uint2(l01, l23);
            }
        }
        if (tid < 64) kseq[tid] = seqb[kt * 64 + tid];
        __syncthreads();

        // S = Q K^T  (3-term bf16x2)
        float S[8][4] = {};
#pragma unroll
        for (int ds = 0; ds < 4; ds++) {
            uint32_t ah[4], al[4];
            int row = wid * 16 + (lane & 15);
            uint32_t ad = qB + row * 256 + ((ds * 32 + (lane >> 4) * 16) ^ ((row & 7) << 4));
            ldsm4(ad, ah[0], ah[1], ah[2], ah[3]);
            ldsm4(ad + 128, al[0], al[1], al[2], al[3]);
#pragma unroll
            for (int np = 0; np < 4; np++) {
                int ntile = np * 2 + (lane >> 4);
                int kpos = ntile * 8 + (lane & 7);
                int dbyte = ds * 32 + ((lane >> 3) & 1) * 16;
                uint32_t kd = kB + kpos * 256 + (dbyte ^ ((kpos & 7) << 4));
                uint32_t bh0, bh1, bh2, bh3, bl0, bl1, bl2, bl3;
                ldsm4(kd, bh0, bh1, bh2, bh3);
                ldsm4(kd + 128, bl0, bl1, bl2, bl3);
                mma16(S[np * 2],     ah, bh0, bh1);
                mma16(S[np * 2],     al, bh0, bh1);
                mma16(S[np * 2],     ah, bl0, bl1);
                mma16(S[np * 2 + 1], ah, bh2, bh3);
                mma16(S[np * 2 + 1], al, bh2, bh3);
                mma16(S[np * 2 + 1], ah, bl2, bl3);
            }
        }
        // mask + scale + online softmax
        float mx0 = -1e30f, mx1 = -1e30f;
#pragma unroll
        for (int nt = 0; nt < 8; nt++) {
            int k0 = kseq[nt * 8 + c0], k1 = kseq[nt * 8 + c0 + 1];
            S[nt][0] = (qs0 == k0) ? S[nt][0] * 0.125f : -1e30f;
            S[nt][1] = (qs0 == k1) ? S[nt][1] * 0.125f : -1e30f;
            S[nt][2] = (qs1 == k0) ? S[nt][2] * 0.125f : -1e30f;
            S[nt][3] = (qs1 == k1) ? S[nt][3] * 0.125f : -1e30f;
            mx0 = fmaxf(mx0, fmaxf(S[nt][0], S[nt][1]));
            mx1 = fmaxf(mx1, fmaxf(S[nt][2], S[nt][3]));
        }
        mx0 = fmaxf(mx0, __shfl_xor_sync(0xffffffffu, mx0, 1));
        mx0 = fmaxf(mx0, __shfl_xor_sync(0xffffffffu, mx0, 2));
        mx1 = fmaxf(mx1, __shfl_xor_sync(0xffffffffu, mx1, 1));
        mx1 = fmaxf(mx1, __shfl_xor_sync(0xffffffffu, mx1, 2));
        float mn0 = fmaxf(m0v, mx0), mn1 = fmaxf(m1v, mx1);
        float al0 = __expf(m0v - mn0), al1 = __expf(m1v - mn1);
        m0v = mn0; m1v = mn1;

        int r = wid * 16 + (lane >> 2);
        int r2 = r + 8;
        float rs0 = 0.f, rs1 = 0.f;
#pragma unroll
        for (int nt = 0; nt < 8; nt++) {
            float p00 = (S[nt][0] <= -9e29f) ? 0.f : __expf(S[nt][0] - mn0);
            float p01 = (S[nt][1] <= -9e29f) ? 0.f : __expf(S[nt][1] - mn0);
            float p10 = (S[nt][2] <= -9e29f) ? 0.f : __expf(S[nt][2] - mn1);
            float p11 = (S[nt][3] <= -9e29f) ? 0.f : __expf(S[nt][3] - mn1);
            rs0 += p00 + p01;
            rs1 += p10 + p11;
            int c = nt * 8 + c0;
            float h00, lo00, h01v, lo01, h10, lo10, h11v, lo11;
            hl(p00, h00, lo00); hl(p01, h01v, lo01);
            hl(p10, h10, lo10); hl(p11, h11v, lo11);
            int sw0 = (c * 2) ^ ((r & 7) << 4);
            char* pp = Ps + r * 256;
            *(uint32_t*)(pp + sw0)       = pk(h00, h01v);
            *(uint32_t*)(pp + 128 + sw0) = pk(lo00, lo01);
            int sw2 = (c * 2) ^ ((r2 & 7) << 4);
            char* pp2 = Ps + r2 * 256;
            *(uint32_t*)(pp2 + sw2)       = pk(h10, h11v);
            *(uint32_t*)(pp2 + 128 + sw2) = pk(lo10, lo11);
        }
        rs0 += __shfl_xor_sync(0xffffffffu, rs0, 1);
        rs0 += __shfl_xor_sync(0xffffffffu, rs0, 2);
        rs1 += __shfl_xor_sync(0xffffffffu, rs1, 1);
        rs1 += __shfl_xor_sync(0xffffffffu, rs1, 2);
        l0s = l0s * al0 + rs0;
        l1s = l1s * al1 + rs1;
#pragma unroll
        for (int nt = 0; nt < 8; nt++) {
            O[nt][0] *= al0; O[nt][1] *= al0;
            O[nt][2] *= al1; O[nt][3] *= al1;
        }
        __syncwarp();   // P rows are per-warp; cross-lane visibility only

        // O += P V (3-term bf16x2)
#pragma unroll
        for (int ks = 0; ks < 4; ks++) {
            uint32_t ah[4], al[4];
            int row = wid * 16 + (lane & 15);
            uint32_t ad = pB + row * 256 + ((ks * 32 + (lane >> 4) * 16) ^ ((row & 7) << 4));
            ldsm4(ad, ah[0], ah[1], ah[2], ah[3]);
            ldsm4(ad + 128, al[0], al[1], al[2], al[3]);
#pragma unroll
            for (int np = 0; np < 4; np++) {
                int kpos = ks * 16 + ((lane >> 3) & 1) * 8 + (lane & 7);
                int dtile = np * 2 + (lane >> 4);
                uint32_t vd = vB + kpos * 256 + ((dtile * 16) ^ ((kpos & 7) << 4));
                uint32_t bh0, bh1, bh2, bh3, bl0, bl1, bl2, bl3;
                ldsm4t(vd, bh0, bh1, bh2, bh3);
                ldsm4t(vd + 128, bl0, bl1, bl2, bl3);
                mma16(O[np * 2],     ah, bh0, bh1);
                mma16(O[np * 2],     al, bh0, bh1);
                mma16(O[np * 2],     ah, bl0, bl1);
                mma16(O[np * 2 + 1], ah, bh2, bh3);
                mma16(O[np * 2 + 1], al, bh2, bh3);
                mma16(O[np * 2 + 1], ah, bl2, bl3);
            }
        }
    }
    // epilogue
    float inv0 = 1.0f / l0s, inv1 = 1.0f / l1s;
    int r0 = q0 + wid * 16 + (lane >> 2);
    float* obase = g_ctx + (rowOff + r0) * D_ + h * DH_ + (lane & 3) * 2;
#pragma unroll
    for (int nt = 0; nt < 8; nt++) {
        *(float2*)(obase + nt * 8) =
            make_float2(O[nt][0] * inv0, O[nt][1] * inv0);
        *(float2*)(obase + (size_t)8 * D_ + nt * 8) =
            make_float2(O[nt][2] * inv1, O[nt][3] * inv1);
    }
}

// ---------------- launch ------------------------------------------------------
extern "C" void kernel_launch(void* const* d_in, const int* in_sizes, int n_in,
                              void* d_out, int out_size) {
    const float* x    = (const float*)d_in[0];
    const int*   seq  = (const int*)d_in[1];
    const float* ln1w = (const float*)d_in[2];
    const float* ln1b = (const float*)d_in[3];
    const float* wqkv = (const float*)d_in[4];
    const float* qlnw = (const float*)d_in[5];
    const float* klnw = (const float*)d_in[6];
    const float* wout = (const float*)d_in[7];
    float* out = (float*)d_out;

    cudaFuncSetAttribute(attn_kernel,
                         cudaFuncAttributeMaxDynamicSharedMemorySize, ATTN_SMEM);

    rope_tab_kernel<<<L_, 32>>>();
    ln1_kernel<<<R_, 256>>>(x, ln1w, ln1b);
    gemm_qkv_kernel<<<dim3(D3_ / 128, R_ / 128), 256>>>(wqkv);
    qkln_rope_kernel<<<dim3(R_, 2), 256>>>(qlnw, klnw);
    attn_kernel<<<dim3(L_ / 128, H_, B_), 256, ATTN_SMEM>>>(seq);
    gemm_out_kernel<<<dim3(D_ / 128, R_ / 128), 256>>>(wout, out);
}

// round 6
// speedup vs baseline: 5.1311x; 1.2310x over previous
#include <cuda_runtime.h>
#include <cuda_bf16.h>
#include <math.h>
#include <stdint.h>

#define B_  2
#define L_  2048
#define D_  1024
#define H_  16
#define DH_ 64
#define R_  (B_ * L_)
#define D3_ (3 * D_)

// ---------------- scratch ----------------------------------------------------
__device__ float g_qkv[(size_t)R_ * D3_];                 // fp32 qkv (gemm out)
__device__ __nv_bfloat16 g_hh[(size_t)R_ * D_];           // LN1 out hi/lo
__device__ __nv_bfloat16 g_hl[(size_t)R_ * D_];
__device__ __nv_bfloat16 g_qh[(size_t)B_ * H_ * L_ * DH_]; // head-major q/k/v/ctx
__device__ __nv_bfloat16 g_ql[(size_t)B_ * H_ * L_ * DH_];
__device__ __nv_bfloat16 g_kh[(size_t)B_ * H_ * L_ * DH_];
__device__ __nv_bfloat16 g_kl[(size_t)B_ * H_ * L_ * DH_];
__device__ __nv_bfloat16 g_vh[(size_t)B_ * H_ * L_ * DH_];
__device__ __nv_bfloat16 g_vl[(size_t)B_ * H_ * L_ * DH_];
__device__ __nv_bfloat16 g_ch[(size_t)B_ * H_ * L_ * DH_];
__device__ __nv_bfloat16 g_cl[(size_t)B_ * H_ * L_ * DH_];
__device__ __nv_bfloat16 g_wqh[(size_t)D_ * D3_];
__device__ __nv_bfloat16 g_wql[(size_t)D_ * D3_];
__device__ __nv_bfloat16 g_woh[(size_t)D_ * D_];
__device__ __nv_bfloat16 g_wol[(size_t)D_ * D_];
__device__ float g_cos[L_ * 32];
__device__ float g_sin[L_ * 32];

// ---------------- helpers ----------------------------------------------------
__device__ __forceinline__ uint32_t pk(float a, float b) {
    __nv_bfloat162 t = __floats2bfloat162_rn(a, b);
    return *reinterpret_cast<uint32_t*>(&t);
}
__device__ __forceinline__ void hl(float x, float& h, float& l) {
    h = __bfloat162float(__float2bfloat16(x));
    l = x - h;
}
__device__ __forceinline__ void cvt4(float4 v, uint32_t& h01, uint32_t& h23,
                                     uint32_t& l01, uint32_t& l23) {
    float hx, lx, hy, ly, hz, lz, hw, lw;
    hl(v.x, hx, lx); hl(v.y, hy, ly); hl(v.z, hz, lz); hl(v.w, hw, lw);
    h01 = pk(hx, hy); h23 = pk(hz, hw);
    l01 = pk(lx, ly); l23 = pk(lz, lw);
}
__device__ __forceinline__ void ldsm4(uint32_t a, uint32_t& r0, uint32_t& r1,
                                      uint32_t& r2, uint32_t& r3) {
    asm volatile("ldmatrix.sync.aligned.m8n8.x4.shared.b16 {%0,%1,%2,%3},[%4];"
                 : "=r"(r0), "=r"(r1), "=r"(r2), "=r"(r3) : "r"(a));
}
__device__ __forceinline__ void ldsm4t(uint32_t a, uint32_t& r0, uint32_t& r1,
                                       uint32_t& r2, uint32_t& r3) {
    asm volatile("ldmatrix.sync.aligned.m8n8.x4.trans.shared.b16 {%0,%1,%2,%3},[%4];"
                 : "=r"(r0), "=r"(r1), "=r"(r2), "=r"(r3) : "r"(a));
}
__device__ __forceinline__ void mma16(float* acc, const uint32_t* a,
                                      uint32_t b0, uint32_t b1) {
    asm volatile(
        "mma.sync.aligned.m16n8k16.row.col.f32.bf16.bf16.f32 "
        "{%0,%1,%2,%3},{%4,%5,%6,%7},{%8,%9},{%0,%1,%2,%3};"
        : "+f"(acc[0]), "+f"(acc[1]), "+f"(acc[2]), "+f"(acc[3])
        : "r"(a[0]), "r"(a[1]), "r"(a[2]), "r"(a[3]), "r"(b0), "r"(b1));
}
__device__ __forceinline__ void cpa16(uint32_t dst, const void* src) {
    asm volatile("cp.async.cg.shared.global [%0], [%1], 16;" :: "r"(dst), "l"(src) : "memory");
}
__device__ __forceinline__ void cp_commit() {
    asm volatile("cp.async.commit_group;" ::: "memory");
}
template<int N> __device__ __forceinline__ void cp_wait() {
    asm volatile("cp.async.wait_group %0;" :: "n"(N) : "memory");
}

// ---------------- RoPE table -------------------------------------------------
__global__ void rope_tab_kernel() {
    int l = blockIdx.x;
    int j = threadIdx.x;
    float inv_f = (float)pow(10000.0, -(double)j / 32.0);
    float ang_f = (float)l * inv_f;
    double a = (double)ang_f;
    g_cos[l * 32 + j] = (float)cos(a);
    g_sin[l * 32 + j] = (float)sin(a);
}

// ---------------- weight fp32 -> bf16 hi/lo ----------------------------------
__global__ void __launch_bounds__(256) convw_kernel(const float* __restrict__ w,
                                                    __nv_bfloat16* __restrict__ wh,
                                                    __nv_bfloat16* __restrict__ wl,
                                                    int n4) {
    int i = blockIdx.x * 256 + threadIdx.x;
    if (i >= n4) return;
    float4 v = ((const float4*)w)[i];
    uint32_t h01, h23, l01, l23;
    cvt4(v, h01, h23, l01, l23);
    ((uint2*)wh)[i] = make_uint2(h01, h23);
    ((uint2*)wl)[i] = make_uint2(l01, l23);
}

// ---------------- LN1: writes bf16 hi/lo -------------------------------------
__global__ void __launch_bounds__(256) ln1_kernel(const float* __restrict__ x,
                                                  const float* __restrict__ w,
                                                  const float* __restrict__ b) {
    __shared__ float sa[8], sb[8];
    int row = blockIdx.x;
    int t = threadIdx.x;
    float4 v = ((const float4*)(x + (size_t)row * D_))[t];
    float s  = v.x + v.y + v.z + v.w;
    float ss = v.x * v.x + v.y * v.y + v.z * v.z + v.w * v.w;
#pragma unroll
    for (int o = 16; o > 0; o >>= 1) {
        s  += __shfl_xor_sync(0xffffffffu, s, o);
        ss += __shfl_xor_sync(0xffffffffu, ss, o);
    }
    if ((t & 31) == 0) { sa[t >> 5] = s; sb[t >> 5] = ss; }
    __syncthreads();
    float ts = 0.f, tss = 0.f;
#pragma unroll
    for (int i = 0; i < 8; i++) { ts += sa[i]; tss += sb[i]; }
    float mu  = ts * (1.0f / D_);
    float var = tss * (1.0f / D_) - mu * mu;
    float rs  = rsqrtf(var + 1e-5f);
    float4 wv = ((const float4*)w)[t];
    float4 bv = ((const float4*)b)[t];
    float4 o;
    o.x = (v.x - mu) * rs * wv.x + bv.x;
    o.y = (v.y - mu) * rs * wv.y + bv.y;
    o.z = (v.z - mu) * rs * wv.z + bv.z;
    o.w = (v.w - mu) * rs * wv.w + bv.w;
    uint32_t h01, h23, l01, l23;
    cvt4(o, h01, h23, l01, l23);
    ((uint2*)(g_hh + (size_t)row * D_))[t] = make_uint2(h01, h23);
    ((uint2*)(g_hl + (size_t)row * D_))[t] = make_uint2(l01, l23);
}

// ---------------- q/k LN + RoPE (+v convert), head-major hi/lo out -----------
__global__ void __launch_bounds__(256) qkln_rope_kernel(const float* __restrict__ qw,
                                                        const float* __restrict__ kw) {
    __shared__ float sa[8], sb[8];
    __shared__ float sv[D_];
    int row = blockIdx.x;
    int which = blockIdx.y;          // 0=q, 1=k, 2=v
    int t = threadIdx.x;
    int bb = row >> 11, l = row & (L_ - 1);

    if (which == 2) {                // v: plain convert to head-major hi/lo
        float4 v = ((const float4*)(g_qkv + (size_t)row * D3_ + 2 * D_))[t];
        uint32_t h01, h23, l01, l23;
        cvt4(v, h01, h23, l01, l23);
        int col = 4 * t, hh = col >> 6, d = col & 63;
        size_t di = (((size_t)(bb * H_ + hh)) * L_ + l) * 64 + d;
        *(uint2*)(g_vh + di) = make_uint2(h01, h23);
        *(uint2*)(g_vl + di) = make_uint2(l01, l23);
        return;
    }
    float* base = g_qkv + (size_t)row * D3_ + which * D_;
    const float* w = which ? kw : qw;

    float4 v = ((const float4*)base)[t];
    float s  = v.x + v.y + v.z + v.w;
    float ss = v.x * v.x + v.y * v.y + v.z * v.z + v.w * v.w;
#pragma unroll
    for (int o = 16; o > 0; o >>= 1) {
        s  += __shfl_xor_sync(0xffffffffu, s, o);
        ss += __shfl_xor_sync(0xffffffffu, ss, o);
    }
    if ((t & 31) == 0) { sa[t >> 5] = s; sb[t >> 5] = ss; }
    __syncthreads();
    float ts = 0.f, tss = 0.f;
#pragma unroll
    for (int i = 0; i < 8; i++) { ts += sa[i]; tss += sb[i]; }
    float mu  = ts * (1.0f / D_);
    float var = tss * (1.0f / D_) - mu * mu;
    float rs  = rsqrtf(var + 1e-5f);
    float4 wv = ((const float4*)w)[t];
    sv[4 * t + 0] = (v.x - mu) * rs * wv.x;
    sv[4 * t + 1] = (v.y - mu) * rs * wv.y;
    sv[4 * t + 2] = (v.z - mu) * rs * wv.z;
    sv[4 * t + 3] = (v.w - mu) * rs * wv.w;
    __syncthreads();

    float res[4];
#pragma unroll
    for (int c = 0; c < 4; c++) {
        int col = 4 * t + c;
        int d = col & 63, dd = d & 31;
        float cs = g_cos[l * 32 + dd];
        float sn = g_sin[l * 32 + dd];
        float y = sv[col];
        res[c] = (d < 32) ? (y * cs - sv[col + 32] * sn)
                          : (y * cs + sv[col - 32] * sn);
    }
    uint32_t h01, h23, l01, l23;
    cvt4(make_float4(res[0], res[1], res[2], res[3]), h01, h23, l01, l23);
    int col = 4 * t, hh = col >> 6, d = col & 63;
    size_t di = (((size_t)(bb * H_ + hh)) * L_ + l) * 64 + d;
    __nv_bfloat16* oh = which ? g_kh : g_qh;
    __nv_bfloat16* ol = which ? g_kl : g_ql;
    *(uint2*)(oh + di) = make_uint2(h01, h23);
    *(uint2*)(ol + di) = make_uint2(l01, l23);
}

// ---------------- bf16x2 GEMM with cp.async, 128x128, BK=64, 3 stages --------
// stage s: Ah s*65536 | Al +16384 | Bh +32768 | Bl +49152  (192 KB)
#define GEMM_SMEM (3 * 65536)

template<bool HEADMAJ>
__device__ __forceinline__ void g_prefetch(uint32_t base, int c, int tid,
        int m0, int n0, int N,
        const __nv_bfloat16* __restrict__ Ahg, const __nv_bfloat16* __restrict__ Alg,
        const __nv_bfloat16* __restrict__ Bhg, const __nv_bfloat16* __restrict__ Blg) {
    uint32_t sb = base + (c % 3) * 65536;
#pragma unroll
    for (int i = 0; i < 4; i++) {
        int id = tid + i * 256;
        {   // A: 128 rows x 8 segs
            int row = id >> 3, sg = id & 7;
            size_t asrc;
            if (HEADMAJ) {
                int gr = m0 + row;
                int bb = gr >> 11, l = gr & (L_ - 1);
                asrc = (((size_t)(bb * H_ + c)) * L_ + l) * 64 + sg * 8;
            } else {
                asrc = (size_t)(m0 + row) * 1024 + c * 64 + sg * 8;
            }
            uint32_t ad = sb + row * 128 + ((sg * 16) ^ ((row & 7) << 4));
            cpa16(ad,         Ahg + asrc);
            cpa16(ad + 16384, Alg + asrc);
        }
        {   // B: 64 k-rows x 16 segs
            int k = id >> 4, sg = id & 15;
            size_t bsrc = (size_t)(c * 64 + k) * N + n0 + sg * 8;
            uint32_t bd = sb + 32768 + k * 256 + ((sg * 16) ^ ((k & 7) << 4));
            cpa16(bd,         Bhg + bsrc);
            cpa16(bd + 16384, Blg + bsrc);
        }
    }
    cp_commit();
}

template<bool HEADMAJ>
__global__ void __launch_bounds__(256) gemm_tc(
        const __nv_bfloat16* __restrict__ Ahg, const __nv_bfloat16* __restrict__ Alg,
        const __nv_bfloat16* __restrict__ Bhg, const __nv_bfloat16* __restrict__ Blg,
        float* __restrict__ C, int N) {
    extern __shared__ __align__(16) char sm[];
    uint32_t base = (uint32_t)__cvta_generic_to_shared(sm);
    int tid = threadIdx.x, wid = tid >> 5, lane = tid & 31;
    int wm = wid >> 1, wn = wid & 1;
    int m0 = blockIdx.y * 128, n0 = blockIdx.x * 128;

    g_prefetch<HEADMAJ>(base, 0, tid, m0, n0, N, Ahg, Alg, Bhg, Blg);
    g_prefetch<HEADMAJ>(base, 1, tid, m0, n0, N, Ahg, Alg, Bhg, Blg);

    float acc[2][8][4] = {};
    for (int c = 0; c < 16; c++) {
        if (c < 15) cp_wait<1>(); else cp_wait<0>();
        __syncthreads();
        uint32_t sb = base + (c % 3) * 65536;
#pragma unroll
        for (int ks = 0; ks < 4; ks++) {
            uint32_t ah[2][4], al[2][4];
#pragma unroll
            for (int mt = 0; mt < 2; mt++) {
                int row = wm * 32 + mt * 16 + (lane & 15);
                uint32_t ad = sb + row * 128 +
                              ((ks * 32 + (lane >> 4) * 16) ^ ((row & 7) << 4));
                ldsm4(ad,         ah[mt][0], ah[mt][1], ah[mt][2], ah[mt][3]);
                ldsm4(ad + 16384, al[mt][0], al[mt][1], al[mt][2], al[mt][3]);
            }
#pragma unroll
            for (int np = 0; np < 4; np++) {
                int k = ks * 16 + (lane & 15);
                int ntile = wn * 8 + np * 2 + (lane >> 4);
                uint32_t bd = sb + 32768 + k * 256 + ((ntile * 16) ^ ((k & 7) << 4));
                uint32_t bh0, bh1, bh2, bh3, bl0, bl1, bl2, bl3;
                ldsm4t(bd,         bh0, bh1, bh2, bh3);
                ldsm4t(bd + 16384, bl0, bl1, bl2, bl3);
#pragma unroll
                for (int mt = 0; mt < 2; mt++) {
                    mma16(acc[mt][np * 2],     ah[mt], bh0, bh1);
                    mma16(acc[mt][np * 2],     al[mt], bh0, bh1);
                    mma16(acc[mt][np * 2],     ah[mt], bl0, bl1);
                    mma16(acc[mt][np * 2 + 1], ah[mt], bh2, bh3);
                    mma16(acc[mt][np * 2 + 1], al[mt], bh2, bh3);
                    mma16(acc[mt][np * 2 + 1], ah[mt], bl2, bl3);
                }
            }
        }
        if (c + 2 < 16)
            g_prefetch<HEADMAJ>(base, c + 2, tid, m0, n0, N, Ahg, Alg, Bhg, Blg);
    }
#pragma unroll
    for (int mt = 0; mt < 2; mt++) {
        int r = m0 + wm * 32 + mt * 16 + (lane >> 2);
        int cc = n0 + wn * 64 + (lane & 3) * 2;
#pragma unroll
        for (int nt = 0; nt < 8; nt++) {
            *(float2*)(C + (size_t)r * N + cc + nt * 8) =
                make_float2(acc[mt][nt][0], acc[mt][nt][1]);
            *(float2*)(C + (size_t)(r + 8) * N + cc + nt * 8) =
                make_float2(acc[mt][nt][2], acc[mt][nt][3]);
        }
    }
}

// ---------------- flash attention: cp.async bf16 hi/lo, 128q x 64k -----------
// smem: Qh 0 | Ql 16384 | Kh 32768 | Kl 40960 | Vh 49152 | Vl 57344 |
//       P 65536 (32768, 256B pitch hi|lo) | kseq 98304
#define ATTN_SMEM 98560

__global__ void __launch_bounds__(256) attn_kernel(const int* __restrict__ seq_id) {
    extern __shared__ __align__(16) char smA[];
    char* Ps = smA + 65536;
    int* kseq = (int*)(smA + 98304);
    uint32_t base = (uint32_t)__cvta_generic_to_shared(smA);
    uint32_t qB = base, kB = base + 32768, vB = base + 49152, pB = base + 65536;

    int qt = blockIdx.x, h = blockIdx.y, b = blockIdx.z;
    int tid = threadIdx.x, wid = tid >> 5, lane = tid & 31;
    int q0 = qt * 128;
    size_t bh = (size_t)(b * H_ + h);
    const int* seqb = seq_id + b * L_;

    // Q tile (128 x 64) hi/lo via cp.async
#pragma unroll
    for (int i = 0; i < 4; i++) {
        int id = tid + i * 256;              // 0..1023
        int q = id >> 3, sg = id & 7;
        size_t src = (bh * L_ + q0 + q) * 64 + sg * 8;
        uint32_t ad = qB + q * 128 + ((sg * 16) ^ ((q & 7) << 4));
        cpa16(ad,         g_qh + src);
        cpa16(ad + 16384, g_ql + src);
    }
    cp_commit();

    int qs0 = seqb[q0 + wid * 16 + (lane >> 2)];
    int qs1 = seqb[q0 + wid * 16 + (lane >> 2) + 8];

    // valid key range (seq_id sorted)
    int sa = seqb[q0], sb2 = seqb[q0 + 127];
    int lo = 0, hi = L_;
    while (lo < hi) { int mid = (lo + hi) >> 1; if (seqb[mid] < sa) lo = mid + 1; else hi = mid; }
    int klo = lo;
    lo = 0; hi = L_;
    while (lo < hi) { int mid = (lo + hi) >> 1; if (seqb[mid] <= sb2) lo = mid + 1; else hi = mid; }
    int khi = lo;
    int kt0 = klo >> 6, kt1 = (khi - 1) >> 6;

    float O[8][4] = {};
    float m0v = -1e30f, m1v = -1e30f, l0s = 0.f, l1s = 0.f;
    int c0 = (lane & 3) * 2;

    for (int kt = kt0; kt <= kt1; kt++) {
        __syncthreads();                      // prior PV done with V; K free
#pragma unroll
        for (int i = 0; i < 2; i++) {
            int id = tid + i * 256;           // 0..511
            int kp = id >> 3, sg = id & 7;
            size_t src = (bh * L_ + kt * 64 + kp) * 64 + sg * 8;
            uint32_t kd = kB + kp * 128 + ((sg * 16) ^ ((kp & 7) << 4));
            cpa16(kd,        g_kh + src);
            cpa16(kd + 8192, g_kl + src);
            uint32_t vd = vB + kp * 128 + ((sg * 16) ^ ((kp & 7) << 4));
            cpa16(vd,        g_vh + src);
            cpa16(vd + 8192, g_vl + src);
        }
        cp_commit();
        if (tid < 64) kseq[tid] = seqb[kt * 64 + tid];
        cp_wait<0>();
        __syncthreads();

        // S = Q K^T (3-term)
        float S[8][4] = {};
#pragma unroll
        for (int ds = 0; ds < 4; ds++) {
            uint32_t ah[4], al[4];
            int row = wid * 16 + (lane & 15);
            uint32_t ad = qB + row * 128 +
                          ((ds * 32 + (lane >> 4) * 16) ^ ((row & 7) << 4));
            ldsm4(ad,         ah[0], ah[1], ah[2], ah[3]);
            ldsm4(ad + 16384, al[0], al[1], al[2], al[3]);
#pragma unroll
            for (int np = 0; np < 4; np++) {
                int kpos = (np * 2 + (lane >> 4)) * 8 + (lane & 7);
                int dbyte = ds * 32 + ((lane >> 3) & 1) * 16;
                uint32_t kd = kB + kpos * 128 + (dbyte ^ ((kpos & 7) << 4));
                uint32_t bh0, bh1, bh2, bh3, bl0, bl1, bl2, bl3;
                ldsm4(kd,        bh0, bh1, bh2, bh3);
                ldsm4(kd + 8192, bl0, bl1, bl2, bl3);
                mma16(S[np * 2],     ah, bh0, bh1);
                mma16(S[np * 2],     al, bh0, bh1);
                mma16(S[np * 2],     ah, bl0, bl1);
                mma16(S[np * 2 + 1], ah, bh2, bh3);
                mma16(S[np * 2 + 1], al, bh2, bh3);
                mma16(S[np * 2 + 1], ah, bl2, bl3);
            }
        }
        // mask + scale + online softmax
        float mx0 = -1e30f, mx1 = -1e30f;
#pragma unroll
        for (int nt = 0; nt < 8; nt++) {
            int k0 = kseq[nt * 8 + c0], k1 = kseq[nt * 8 + c0 + 1];
            S[nt][0] = (qs0 == k0) ? S[nt][0] * 0.125f : -1e30f;
            S[nt][1] = (qs0 == k1) ? S[nt][1] * 0.125f : -1e30f;
            S[nt][2] = (qs1 == k0) ? S[nt][2] * 0.125f : -1e30f;
            S[nt][3] = (qs1 == k1) ? S[nt][3] * 0.125f : -1e30f;
            mx0 = fmaxf(mx0, fmaxf(S[nt][0], S[nt][1]));
            mx1 = fmaxf(mx1, fmaxf(S[nt][2], S[nt][3]));
        }
        mx0 = fmaxf(mx0, __shfl_xor_sync(0xffffffffu, mx0, 1));
        mx0 = fmaxf(mx0, __shfl_xor_sync(0xffffffffu, mx0, 2));
        mx1 = fmaxf(mx1, __shfl_xor_sync(0xffffffffu, mx1, 1));
        mx1 = fmaxf(mx1, __shfl_xor_sync(0xffffffffu, mx1, 2));
        float mn0 = fmaxf(m0v, mx0), mn1 = fmaxf(m1v, mx1);
        float al0 = __expf(m0v - mn0), al1 = __expf(m1v - mn1);
        m0v = mn0; m1v = mn1;

        int r = wid * 16 + (lane >> 2);
        int r2 = r + 8;
        float rs0 = 0.f, rs1 = 0.f;
#pragma unroll
        for (int nt = 0; nt < 8; nt++) {
            float p00 = (S[nt][0] <= -9e29f) ? 0.f : __expf(S[nt][0] - mn0);
            float p01 = (S[nt][1] <= -9e29f) ? 0.f : __expf(S[nt][1] - mn0);
            float p10 = (S[nt][2] <= -9e29f) ? 0.f : __expf(S[nt][2] - mn1);
            float p11 = (S[nt][3] <= -9e29f) ? 0.f : __expf(S[nt][3] - mn1);
            rs0 += p00 + p01;
            rs1 += p10 + p11;
            int c = nt * 8 + c0;
            float h00, lo00, h01v, lo01, h10, lo10, h11v, lo11;
            hl(p00, h00, lo00); hl(p01, h01v, lo01);
            hl(p10, h10, lo10); hl(p11, h11v, lo11);
            int sw0 = (c * 2) ^ ((r & 7) << 4);
            char* pp = Ps + r * 256;
            *(uint32_t*)(pp + sw0)       = pk(h00, h01v);
            *(uint32_t*)(pp + 128 + sw0) = pk(lo00, lo01);
            int sw2 = (c * 2) ^ ((r2 & 7) << 4);
            char* pp2 = Ps + r2 * 256;
            *(uint32_t*)(pp2 + sw2)       = pk(h10, h11v);
            *(uint32_t*)(pp2 + 128 + sw2) = pk(lo10, lo11);
        }
        rs0 += __shfl_xor_sync(0xffffffffu, rs0, 1);
        rs0 += __shfl_xor_sync(0xffffffffu, rs0, 2);
        rs1 += __shfl_xor_sync(0xffffffffu, rs1, 1);
        rs1 += __shfl_xor_sync(0xffffffffu, rs1, 2);
        l0s = l0s * al0 + rs0;
        l1s = l1s * al1 + rs1;
#pragma unroll
        for (int nt = 0; nt < 8; nt++) {
            O[nt][0] *= al0; O[nt][1] *= al0;
            O[nt][2] *= al1; O[nt][3] *= al1;
        }
        __syncwarp();

        // O += P V (3-term)
#pragma unroll
        for (int ks = 0; ks < 4; ks++) {
            uint32_t ah[4], al[4];
            int row = wid * 16 + (lane & 15);
            uint32_t ad = pB + row * 256 +
                          ((ks * 32 + (lane >> 4) * 16) ^ ((row & 7) << 4));
            ldsm4(ad,       ah[0], ah[1], ah[2], ah[3]);
            ldsm4(ad + 128, al[0], al[1], al[2], al[3]);
#pragma unroll
            for (int np = 0; np < 4; np++) {
                int kpos = ks * 16 + ((lane >> 3) & 1) * 8 + (lane & 7);
                int dtile = np * 2 + (lane >> 4);
                uint32_t vd = vB + kpos * 128 + ((dtile * 16) ^ ((kpos & 7) << 4));
                uint32_t bh0, bh1, bh2, bh3, bl0, bl1, bl2, bl3;
                ldsm4t(vd,        bh0, bh1, bh2, bh3);
                ldsm4t(vd + 8192, bl0, bl1, bl2, bl3);
                mma16(O[np * 2],     ah, bh0, bh1);
                mma16(O[np * 2],     al, bh0, bh1);
                mma16(O[np * 2],     ah, bl0, bl1);
                mma16(O[np * 2 + 1], ah, bh2, bh3);
                mma16(O[np * 2 + 1], al, bh2, bh3);
                mma16(O[np * 2 + 1], ah, bl2, bl3);
            }
        }
    }
    // epilogue: write ctx bf16 hi/lo, head-major
    float inv0 = 1.0f / l0s, inv1 = 1.0f / l1s;
    int r0 = q0 + wid * 16 + (lane >> 2);
    size_t ob = (bh * L_ + r0) * 64 + (lane & 3) * 2;
#pragma unroll
    for (int nt = 0; nt < 8; nt++) {
        float v0 = O[nt][0] * inv0, v1 = O[nt][1] * inv0;
        float v2 = O[nt][2] * inv1, v3 = O[nt][3] * inv1;
        float h0, lo0, h1, lo1, h2, lo2, h3, lo3;
        hl(v0, h0, lo0); hl(v1, h1, lo1); hl(v2, h2, lo2); hl(v3, h3, lo3);
        *(uint32_t*)(g_ch + ob + nt * 8) = pk(h0, h1);
        *(uint32_t*)(g_cl + ob + nt * 8) = pk(lo0, lo1);
        *(uint32_t*)(g_ch + ob + (size_t)8 * 64 + nt * 8) = pk(h2, h3);
        *(uint32_t*)(g_cl + ob + (size_t)8 * 64 + nt * 8) = pk(lo2, lo3);
    }
}

// ---------------- launch ------------------------------------------------------
extern "C" void kernel_launch(void* const* d_in, const int* in_sizes, int n_in,
                              void* d_out, int out_size) {
    const float* x    = (const float*)d_in[0];
    const int*   seq  = (const int*)d_in[1];
    const float* ln1w = (const float*)d_in[2];
    const float* ln1b = (const float*)d_in[3];
    const float* wqkv = (const float*)d_in[4];
    const float* qlnw = (const float*)d_in[5];
    const float* klnw = (const float*)d_in[6];
    const float* wout = (const float*)d_in[7];
    float* out = (float*)d_out;

    static __nv_bfloat16 *p_ = nullptr; (void)p_;
    __nv_bfloat16 *hh, *hlp, *wqh, *wql, *woh, *wol, *ch, *cl;
    __nv_bfloat16 *qh, *ql, *kh, *kl, *vh, *vl;
    cudaGetSymbolAddress((void**)&hh,  g_hh);
    cudaGetSymbolAddress((void**)&hlp, g_hl);
    cudaGetSymbolAddress((void**)&wqh, g_wqh);
    cudaGetSymbolAddress((void**)&wql, g_wql);
    cudaGetSymbolAddress((void**)&woh, g_woh);
    cudaGetSymbolAddress((void**)&wol, g_wol);
    cudaGetSymbolAddress((void**)&ch,  g_ch);
    cudaGetSymbolAddress((void**)&cl,  g_cl);
    cudaGetSymbolAddress((void**)&qh,  g_qh);
    cudaGetSymbolAddress((void**)&ql,  g_ql);
    cudaGetSymbolAddress((void**)&kh,  g_kh);
    cudaGetSymbolAddress((void**)&kl,  g_kl);
    cudaGetSymbolAddress((void**)&vh,  g_vh);
    cudaGetSymbolAddress((void**)&vl,  g_vl);
    float* qkvp;
    cudaGetSymbolAddress((void**)&qkvp, g_qkv);

    cudaFuncSetAttribute(gemm_tc<false>,
                         cudaFuncAttributeMaxDynamicSharedMemorySize, GEMM_SMEM);
    cudaFuncSetAttribute(gemm_tc<true>,
                         cudaFuncAttributeMaxDynamicSharedMemorySize, GEMM_SMEM);
    cudaFuncSetAttribute(attn_kernel,
                         cudaFuncAttributeMaxDynamicSharedMemorySize, ATTN_SMEM);

    rope_tab_kernel<<<L_, 32>>>();
    convw_kernel<<<(D_ * D3_ / 4 + 255) / 256, 256>>>(wqkv, wqh, wql, D_ * D3_ / 4);
    convw_kernel<<<(D_ * D_ / 4 + 255) / 256, 256>>>(wout, woh, wol, D_ * D_ / 4);
    ln1_kernel<<<R_, 256>>>(x, ln1w, ln1b);
    gemm_tc<false><<<dim3(D3_ / 128, R_ / 128), 256, GEMM_SMEM>>>(
        hh, hlp, wqh, wql, qkvp, D3_);
    qkln_rope_kernel<<<dim3(R_, 3), 256>>>(qlnw, klnw);
    attn_kernel<<<dim3(L_ / 128, H_, B_), 256, ATTN_SMEM>>>(seq);
    gemm_tc<true><<<dim3(D_ / 128, R_ / 128), 256, GEMM_SMEM>>>(
        ch, cl, woh, wol, out, D_);
}